// round 16
// baseline (speedup 1.0000x reference)
#include <cuda_runtime.h>
#include <cuda_fp16.h>
#include <cstdint>

#define S_DIM 512
#define O_DIM 4096
#define I_DIM 4096

#define WSPLIT_BLOCKS 8192            // 8192 blocks x 256 thr x 8 elem = 16M
#define PREP_BLOCKS   (WSPLIT_BLOCKS + S_DIM)

// ===================== device-global scratch ===============================
__device__ float g_D[S_DIM];
__device__ int   g_anyC2 = 0;   // zero-init; atomicOr idempotent across replays

// fp16 operand matrices (g_A2/g_Rh stay zero where never written)
__device__ __align__(16) __half g_A1 [S_DIM * O_DIM];
__device__ __align__(16) __half g_A2 [S_DIM * O_DIM];
__device__ __align__(16) __half g_Wh [(size_t)O_DIM * I_DIM];
__device__ __align__(16) __half g_Rh [(size_t)O_DIM * I_DIM];

__device__ __forceinline__ uint32_t smem_u32(const void* p) {
    uint32_t a;
    asm("{ .reg .u64 t; cvta.to.shared.u64 t, %1; cvt.u32.u64 %0, t; }"
        : "=r"(a) : "l"(p));
    return a;
}
#define CP_ASYNC16(s, g) \
    asm volatile("cp.async.cg.shared.global [%0], [%1], 16;" :: "r"(s), "l"(g))
#define CP_COMMIT() asm volatile("cp.async.commit_group;" ::: "memory")
#define CP_WAIT2()  asm volatile("cp.async.wait_group 2;" ::: "memory")

__device__ __forceinline__ void ldmx4(uint32_t* r, uint32_t addr) {
    asm volatile("ldmatrix.sync.aligned.m8n8.x4.shared.b16 {%0,%1,%2,%3}, [%4];"
                 : "=r"(r[0]), "=r"(r[1]), "=r"(r[2]), "=r"(r[3]) : "r"(addr));
}
__device__ __forceinline__ void ldmx2t(uint32_t* r, uint32_t addr) {
    asm volatile("ldmatrix.sync.aligned.m8n8.x2.trans.shared.b16 {%0,%1}, [%2];"
                 : "=r"(r[0]), "=r"(r[1]) : "r"(addr));
}
__device__ __forceinline__ void mma_f16(float* c, const uint32_t* a, const uint32_t* b) {
    asm volatile("mma.sync.aligned.m16n8k16.row.col.f32.f16.f16.f32 "
                 "{%0,%1,%2,%3}, {%4,%5,%6,%7}, {%8,%9}, {%0,%1,%2,%3};"
                 : "+f"(c[0]), "+f"(c[1]), "+f"(c[2]), "+f"(c[3])
                 : "r"(a[0]), "r"(a[1]), "r"(a[2]), "r"(a[3]), "r"(b[0]), "r"(b[1]));
}

// ---- per-neuron scalar derivation (matches reference semantics) -----------
struct NeuronScalars { float P1, N1, P2, PB, NB; };
__device__ __forceinline__ NeuronScalars derive_scalars(float b, float lb,
                                                        float ub, float a) {
    float one_a = 1.0f - a;
    float lb_r = fminf(lb, 0.0f);
    float ub_r = fmaxf(ub, 0.0f);
    ub_r = fmaxf(ub_r, lb_r + 1e-8f);
    float ud  = ub_r / (ub_r - lb_r);
    float upb = -lb_r * ud;
    float ldv = (ud > 0.5f) ? 1.0f : 0.0f;
    float lower_d = (fabsf(lb) >= fabsf(ub)) ? 1.0f : 0.0f;

    NeuronScalars s;
    if (ub <= 0.0f) {
        s.P1 = a * ud;           s.N1 = a * ldv;                    s.P2 = 0.0f;
        s.PB = upb + ud * a * b; s.NB = ldv * a * b;
    } else if (lb >= 0.0f) {
        s.P1 = a * ud + one_a;   s.N1 = a * ldv + one_a;            s.P2 = 0.0f;
        s.PB = one_a * b + upb + ud * a * b;
        s.NB = one_a * b + ldv * a * b;
    } else {
        s.P1 = a * ud;           s.N1 = a * ldv + one_a * lower_d;  s.P2 = one_a;
        s.PB = one_a * fmaxf(b, 0.0f) + upb + ud * a * b;
        s.NB = one_a * lower_d * b + ldv * a * b;
    }
    return s;
}

// ===================== kernel 1: merged prep (wsplit + coeff) ==============
// Blocks [0, WSPLIT_BLOCKS): W -> fp16 (8 elems/thread, 16B stores).
// Blocks [WSPLIT_BLOCKS, +S_DIM): per-spec-row coefficients + ubias + D.
__global__ void __launch_bounds__(256)
kern_prep_all(const float* __restrict__ W,
              const float* __restrict__ bias,
              const float* __restrict__ lbp,
              const float* __restrict__ ubp,
              const float* __restrict__ alpha,
              const float* __restrict__ last_uA,
              float* __restrict__ ubias_out) {
    if (blockIdx.x < WSPLIT_BLOCKS) {
        // -------- W split: 8 consecutive elements of one row o ------------
        size_t base = ((size_t)blockIdx.x * 256 + threadIdx.x) * 8;
        int o = (int)(base >> 12);               // base / 4096
        float4 w0 = *(const float4*)(W + base);
        float4 w1 = *(const float4*)(W + base + 4);
        __half2 h[4];
        h[0] = {__float2half_rn(w0.x), __float2half_rn(w0.y)};
        h[1] = {__float2half_rn(w0.z), __float2half_rn(w0.w)};
        h[2] = {__float2half_rn(w1.x), __float2half_rn(w1.y)};
        h[3] = {__float2half_rn(w1.z), __float2half_rn(w1.w)};
        *(uint4*)(g_Wh + base) = *(uint4*)h;

        // relu(W+b) row only for unstable neurons with alpha != 1
        float lb = __ldg(lbp + o), ub = __ldg(ubp + o), a = __ldg(alpha + o);
        if (lb < 0.0f && ub > 0.0f && a != 1.0f) {
            float b = __ldg(bias + o);
            __half2 r[4];
            r[0] = {__float2half_rn(fmaxf(w0.x + b, 0.0f)),
                    __float2half_rn(fmaxf(w0.y + b, 0.0f))};
            r[1] = {__float2half_rn(fmaxf(w0.z + b, 0.0f)),
                    __float2half_rn(fmaxf(w0.w + b, 0.0f))};
            r[2] = {__float2half_rn(fmaxf(w1.x + b, 0.0f)),
                    __float2half_rn(fmaxf(w1.y + b, 0.0f))};
            r[3] = {__float2half_rn(fmaxf(w1.z + b, 0.0f)),
                    __float2half_rn(fmaxf(w1.w + b, 0.0f))};
            *(uint4*)(g_Rh + base) = *(uint4*)r;
        }
        return;
    }

    // -------- coefficient pass: one spec row per block --------------------
    int s = blockIdx.x - WSPLIT_BLOCKS;
    const float* row = last_uA + (size_t)s * O_DIM;

    float accB = 0.0f, accD = 0.0f;
    bool anyc2 = false;
    for (int o = threadIdx.x; o < O_DIM; o += 256) {
        float u  = row[o];
        float b  = __ldg(bias + o);
        float lb = __ldg(lbp + o);
        float ub = __ldg(ubp + o);
        float a  = __ldg(alpha + o);
        NeuronScalars ns = derive_scalars(b, lb, ub, a);

        float p = fmaxf(u, 0.0f);
        float n = fminf(u, 0.0f);
        float c1 = p * ns.P1 + n * ns.N1;
        size_t idx = (size_t)s * O_DIM + o;
        g_A1[idx] = __float2half_rn(c1);
        if (ns.P2 != 0.0f) {                 // g_A2 stays 0 elsewhere (c2=0)
            float c2 = p * ns.P2;
            g_A2[idx] = __float2half_rn(c2);
            accD = fmaf(c2, -fmaxf(b, 0.0f), accD);
            anyc2 = true;
        }
        accB = fmaf(p, ns.PB, accB);
        accB = fmaf(n, ns.NB, accB);
    }
    if (__ballot_sync(0xffffffffu, anyc2) && (threadIdx.x & 31) == 0)
        atomicOr(&g_anyC2, 1);

    __shared__ float sB[8], sD[8];
    #pragma unroll
    for (int off = 16; off > 0; off >>= 1) {
        accB += __shfl_down_sync(0xffffffffu, accB, off);
        accD += __shfl_down_sync(0xffffffffu, accD, off);
    }
    int wid = threadIdx.x >> 5, lid = threadIdx.x & 31;
    if (lid == 0) { sB[wid] = accB; sD[wid] = accD; }
    __syncthreads();
    if (threadIdx.x == 0) {
        float tB = 0.0f, tD = 0.0f;
        #pragma unroll
        for (int w = 0; w < 8; w++) { tB += sB[w]; tD += sD[w]; }
        ubias_out[s] = tB;
        g_D[s] = tD;
    }
}

// ===================== kernel 2: mma.sync fp16 GEMM (R13 config) ===========
// out[m,i] = sum_o fp16(C1)[m,o]*fp16(W)[o,i] (+ C2 path) + D[m]
// BM=128 x BN=128, 512 threads (4 warps/SMSP), grid 128, 4-stage pipeline.
#define BM 128
#define BN 128
#define BK 64
#define NTHR 512
#define LDA 72            // (BK+8) fp16 elems, 144 bytes/row
#define LDB 136           // (BN+8) fp16 elems, 272 bytes/row
#define A_BYTES (BM * LDA * 2)        // 18432
#define B_BYTES (BK * LDB * 2)        // 17408
#define STAGE   (A_BYTES + B_BYTES)   // 35840
#define NSTAGE  4
#define SMEM_DYN (NSTAGE * STAGE)     // 143360

__global__ void __launch_bounds__(NTHR, 1)
kern_gemm_mma(float* __restrict__ out) {
    extern __shared__ char sm[];
    const uint32_t sbase = smem_u32(sm);

    const int tid  = threadIdx.x;
    const int wid  = tid >> 5;
    const int lane = tid & 31;
    const int bn = blockIdx.x * BN;
    const int bm = blockIdx.y * BM;
    const bool useC2 = (g_anyC2 != 0);
    const int nK = useC2 ? 128 : 64;

    const int warp_m = wid & 3;      // 0..3 -> 32 rows each
    const int warp_n = wid >> 2;     // 0..3 -> 32 cols each

    float acc[2][4][4];
    #pragma unroll
    for (int mi = 0; mi < 2; mi++)
        #pragma unroll
        for (int ni = 0; ni < 4; ni++)
            #pragma unroll
            for (int q = 0; q < 4; q++) acc[mi][ni][q] = 0.0f;

    auto load_stage = [&](int ktL) {
        const int buf = ktL & (NSTAGE - 1);
        const int k0 = (ktL & 63) * BK;
        const __half *pA, *pB;
        if (ktL < 64) { pA = g_A1; pB = g_Wh; }
        else          { pA = g_A2; pB = g_Rh; }
        const uint32_t sA = sbase + buf * STAGE;
        const uint32_t sB = sA + A_BYTES;

        #pragma unroll
        for (int j = 0; j < 2; j++) {           // A: 128 rows x 8 chunks
            int id = tid + NTHR * j;
            int ar = id >> 3, ac = id & 7;
            size_t gA = (size_t)(bm + ar) * O_DIM + k0 + ac * 8;
            CP_ASYNC16(sA + ar * (LDA * 2) + ac * 16, pA + gA);
        }
        #pragma unroll
        for (int j = 0; j < 2; j++) {           // B: 64 rows x 16 chunks
            int id = tid + NTHR * j;
            int br = id >> 4, bc = id & 15;
            size_t gB = (size_t)(k0 + br) * I_DIM + bn + bc * 8;
            CP_ASYNC16(sB + br * (LDB * 2) + bc * 16, pB + gB);
        }
    };

    // prologue: fill 3 of 4 stages
    load_stage(0); CP_COMMIT();
    load_stage(1); CP_COMMIT();
    load_stage(2); CP_COMMIT();

    const uint32_t aoff = (warp_m * 32 + (lane & 15)) * (LDA * 2) + (lane >> 4) * 16;
    const uint32_t boff = (lane & 15) * (LDB * 2) + warp_n * 64;

    for (int kt = 0; kt < nK; kt++) {
        // Outstanding groups (this thread): loads kt, kt+1, kt+2.
        CP_WAIT2();             // my stage-kt copies retired
        __syncthreads();        // everyone's stage-kt data visible;
                                // all threads done with compute(kt-1)
        if (kt + 3 < nK) load_stage(kt + 3);   // overwrites buf (kt-1)%4: safe
        CP_COMMIT();

        const int buf = kt & (NSTAGE - 1);
        const uint32_t sA = sbase + buf * STAGE;
        const uint32_t sB = sA + A_BYTES;

        #pragma unroll
        for (int ks = 0; ks < 4; ks++) {
            uint32_t ah[2][4], bh[4][2];
            #pragma unroll
            for (int mi = 0; mi < 2; mi++) {
                uint32_t a = aoff + mi * 16 * (LDA * 2) + ks * 32;
                ldmx4(ah[mi], sA + a);
            }
            #pragma unroll
            for (int ni = 0; ni < 4; ni++) {
                uint32_t b = boff + ks * 16 * (LDB * 2) + ni * 16;
                ldmx2t(bh[ni], sB + b);
            }
            #pragma unroll
            for (int mi = 0; mi < 2; mi++)
                #pragma unroll
                for (int ni = 0; ni < 4; ni++)
                    mma_f16(acc[mi][ni], ah[mi], bh[ni]);
        }
    }

    // ---- epilogue: add D[m], write float2 per fragment pair
    #pragma unroll
    for (int mi = 0; mi < 2; mi++) {
        const int r0 = bm + warp_m * 32 + mi * 16 + (lane >> 2);
        const int r1 = r0 + 8;
        const float d0 = g_D[r0];
        const float d1 = g_D[r1];
        #pragma unroll
        for (int ni = 0; ni < 4; ni++) {
            const int c = bn + warp_n * 32 + ni * 8 + (lane & 3) * 2;
            float2 v0 = {acc[mi][ni][0] + d0, acc[mi][ni][1] + d0};
            float2 v1 = {acc[mi][ni][2] + d1, acc[mi][ni][3] + d1};
            *(float2*)(out + (size_t)r0 * I_DIM + c) = v0;
            *(float2*)(out + (size_t)r1 * I_DIM + c) = v1;
        }
    }
}

// ===================== launch ==============================================
extern "C" void kernel_launch(void* const* d_in, const int* in_sizes, int n_in,
                              void* d_out, int out_size) {
    const float* last_uA = (const float*)d_in[0];  // [1, 512, 4096]
    const float* weight  = (const float*)d_in[1];  // [4096, 4096]
    const float* bias    = (const float*)d_in[2];  // [4096]
    const float* lbp     = (const float*)d_in[3];  // [1, 4096]
    const float* ubp     = (const float*)d_in[4];  // [1, 4096]
    const float* alpha   = (const float*)d_in[5];  // [1, 4096, 1]
    float* out = (float*)d_out;                    // uA then ubias

    cudaFuncSetAttribute(kern_gemm_mma,
                         cudaFuncAttributeMaxDynamicSharedMemorySize, SMEM_DYN);

    kern_prep_all<<<PREP_BLOCKS, 256>>>(weight, bias, lbp, ubp, alpha,
                                        last_uA, out + (size_t)S_DIM * I_DIM);
    kern_gemm_mma<<<dim3(I_DIM / BN, S_DIM / BM), NTHR, SMEM_DYN>>>(out);
}

// round 17
// speedup vs baseline: 1.0828x; 1.0828x over previous
#include <cuda_runtime.h>
#include <cuda_fp16.h>
#include <cstdint>

#define S_DIM 512
#define O_DIM 4096
#define I_DIM 4096

#define WSPLIT_BLOCKS 8192            // 8192 blocks x 256 thr x 8 elem = 16M
#define PREP_BLOCKS   (WSPLIT_BLOCKS + S_DIM)

// ===================== device-global scratch ===============================
__device__ float g_D[S_DIM];
__device__ int   g_anyC2 = 0;   // zero-init; atomicOr idempotent across replays

// fp16 operand matrices (g_A2/g_Rh stay zero where never written)
__device__ __align__(16) __half g_A1 [S_DIM * O_DIM];
__device__ __align__(16) __half g_A2 [S_DIM * O_DIM];
__device__ __align__(16) __half g_Wh [(size_t)O_DIM * I_DIM];
__device__ __align__(16) __half g_Rh [(size_t)O_DIM * I_DIM];

__device__ __forceinline__ uint32_t smem_u32(const void* p) {
    uint32_t a;
    asm("{ .reg .u64 t; cvta.to.shared.u64 t, %1; cvt.u32.u64 %0, t; }"
        : "=r"(a) : "l"(p));
    return a;
}
#define CP_ASYNC16(s, g) \
    asm volatile("cp.async.cg.shared.global [%0], [%1], 16;" :: "r"(s), "l"(g))
#define CP_COMMIT() asm volatile("cp.async.commit_group;" ::: "memory")
#define CP_WAIT1()  asm volatile("cp.async.wait_group 1;" ::: "memory")

__device__ __forceinline__ void ldmx4(uint32_t* r, uint32_t addr) {
    asm volatile("ldmatrix.sync.aligned.m8n8.x4.shared.b16 {%0,%1,%2,%3}, [%4];"
                 : "=r"(r[0]), "=r"(r[1]), "=r"(r[2]), "=r"(r[3]) : "r"(addr));
}
__device__ __forceinline__ void ldmx4t(uint32_t* r, uint32_t addr) {
    asm volatile("ldmatrix.sync.aligned.m8n8.x4.trans.shared.b16 {%0,%1,%2,%3}, [%4];"
                 : "=r"(r[0]), "=r"(r[1]), "=r"(r[2]), "=r"(r[3]) : "r"(addr));
}
__device__ __forceinline__ void mma_f16(float* c, const uint32_t* a, const uint32_t* b) {
    asm volatile("mma.sync.aligned.m16n8k16.row.col.f32.f16.f16.f32 "
                 "{%0,%1,%2,%3}, {%4,%5,%6,%7}, {%8,%9}, {%0,%1,%2,%3};"
                 : "+f"(c[0]), "+f"(c[1]), "+f"(c[2]), "+f"(c[3])
                 : "r"(a[0]), "r"(a[1]), "r"(a[2]), "r"(a[3]), "r"(b[0]), "r"(b[1]));
}

// ---- per-neuron scalar derivation (matches reference semantics) -----------
struct NeuronScalars { float P1, N1, P2, PB, NB; };
__device__ __forceinline__ NeuronScalars derive_scalars(float b, float lb,
                                                        float ub, float a) {
    float one_a = 1.0f - a;
    float lb_r = fminf(lb, 0.0f);
    float ub_r = fmaxf(ub, 0.0f);
    ub_r = fmaxf(ub_r, lb_r + 1e-8f);
    float ud  = ub_r / (ub_r - lb_r);
    float upb = -lb_r * ud;
    float ldv = (ud > 0.5f) ? 1.0f : 0.0f;
    float lower_d = (fabsf(lb) >= fabsf(ub)) ? 1.0f : 0.0f;

    NeuronScalars s;
    if (ub <= 0.0f) {
        s.P1 = a * ud;           s.N1 = a * ldv;                    s.P2 = 0.0f;
        s.PB = upb + ud * a * b; s.NB = ldv * a * b;
    } else if (lb >= 0.0f) {
        s.P1 = a * ud + one_a;   s.N1 = a * ldv + one_a;            s.P2 = 0.0f;
        s.PB = one_a * b + upb + ud * a * b;
        s.NB = one_a * b + ldv * a * b;
    } else {
        s.P1 = a * ud;           s.N1 = a * ldv + one_a * lower_d;  s.P2 = one_a;
        s.PB = one_a * fmaxf(b, 0.0f) + upb + ud * a * b;
        s.NB = one_a * lower_d * b + ldv * a * b;
    }
    return s;
}

// ===================== kernel 1: merged prep (wsplit + coeff) ==============
__global__ void __launch_bounds__(256)
kern_prep_all(const float* __restrict__ W,
              const float* __restrict__ bias,
              const float* __restrict__ lbp,
              const float* __restrict__ ubp,
              const float* __restrict__ alpha,
              const float* __restrict__ last_uA,
              float* __restrict__ ubias_out) {
    if (blockIdx.x < WSPLIT_BLOCKS) {
        // -------- W split: 8 consecutive elements of one row o ------------
        size_t base = ((size_t)blockIdx.x * 256 + threadIdx.x) * 8;
        int o = (int)(base >> 12);               // base / 4096
        float4 w0 = *(const float4*)(W + base);
        float4 w1 = *(const float4*)(W + base + 4);
        __half2 h[4];
        h[0] = {__float2half_rn(w0.x), __float2half_rn(w0.y)};
        h[1] = {__float2half_rn(w0.z), __float2half_rn(w0.w)};
        h[2] = {__float2half_rn(w1.x), __float2half_rn(w1.y)};
        h[3] = {__float2half_rn(w1.z), __float2half_rn(w1.w)};
        *(uint4*)(g_Wh + base) = *(uint4*)h;

        float lb = __ldg(lbp + o), ub = __ldg(ubp + o), a = __ldg(alpha + o);
        if (lb < 0.0f && ub > 0.0f && a != 1.0f) {
            float b = __ldg(bias + o);
            __half2 r[4];
            r[0] = {__float2half_rn(fmaxf(w0.x + b, 0.0f)),
                    __float2half_rn(fmaxf(w0.y + b, 0.0f))};
            r[1] = {__float2half_rn(fmaxf(w0.z + b, 0.0f)),
                    __float2half_rn(fmaxf(w0.w + b, 0.0f))};
            r[2] = {__float2half_rn(fmaxf(w1.x + b, 0.0f)),
                    __float2half_rn(fmaxf(w1.y + b, 0.0f))};
            r[3] = {__float2half_rn(fmaxf(w1.z + b, 0.0f)),
                    __float2half_rn(fmaxf(w1.w + b, 0.0f))};
            *(uint4*)(g_Rh + base) = *(uint4*)r;
        }
        return;
    }

    // -------- coefficient pass: one spec row per block --------------------
    int s = blockIdx.x - WSPLIT_BLOCKS;
    const float* row = last_uA + (size_t)s * O_DIM;

    float accB = 0.0f, accD = 0.0f;
    bool anyc2 = false;
    for (int o = threadIdx.x; o < O_DIM; o += 256) {
        float u  = row[o];
        float b  = __ldg(bias + o);
        float lb = __ldg(lbp + o);
        float ub = __ldg(ubp + o);
        float a  = __ldg(alpha + o);
        NeuronScalars ns = derive_scalars(b, lb, ub, a);

        float p = fmaxf(u, 0.0f);
        float n = fminf(u, 0.0f);
        float c1 = p * ns.P1 + n * ns.N1;
        size_t idx = (size_t)s * O_DIM + o;
        g_A1[idx] = __float2half_rn(c1);
        if (ns.P2 != 0.0f) {                 // g_A2 stays 0 elsewhere (c2=0)
            float c2 = p * ns.P2;
            g_A2[idx] = __float2half_rn(c2);
            accD = fmaf(c2, -fmaxf(b, 0.0f), accD);
            anyc2 = true;
        }
        accB = fmaf(p, ns.PB, accB);
        accB = fmaf(n, ns.NB, accB);
    }
    if (__ballot_sync(0xffffffffu, anyc2) && (threadIdx.x & 31) == 0)
        atomicOr(&g_anyC2, 1);

    __shared__ float sB[8], sD[8];
    #pragma unroll
    for (int off = 16; off > 0; off >>= 1) {
        accB += __shfl_down_sync(0xffffffffu, accB, off);
        accD += __shfl_down_sync(0xffffffffu, accD, off);
    }
    int wid = threadIdx.x >> 5, lid = threadIdx.x & 31;
    if (lid == 0) { sB[wid] = accB; sD[wid] = accD; }
    __syncthreads();
    if (threadIdx.x == 0) {
        float tB = 0.0f, tD = 0.0f;
        #pragma unroll
        for (int w = 0; w < 8; w++) { tB += sB[w]; tD += sD[w]; }
        ubias_out[s] = tB;
        g_D[s] = tD;
    }
}

// ===================== kernel 2: mma.sync fp16 GEMM ========================
// out[m,i] = sum_o fp16(C1)[m,o]*fp16(W)[o,i] (+ C2 path) + D[m]
// BM=128 x BN=128, BK=128, 512 threads, 3-stage pipeline, ldmatrix.x4.trans B.
#define BM 128
#define BN 128
#define BK 128
#define NTHR 512
#define LDA 136           // (BK+8) fp16 elems, 272 bytes/row
#define LDB 136           // (BN+8) fp16 elems, 272 bytes/row
#define A_BYTES (BM * LDA * 2)        // 34816
#define B_BYTES (BK * LDB * 2)        // 34816
#define STAGE   (A_BYTES + B_BYTES)   // 69632
#define NSTAGE  3
#define SMEM_DYN (NSTAGE * STAGE)     // 208896

__global__ void __launch_bounds__(NTHR, 1)
kern_gemm_mma(float* __restrict__ out) {
    extern __shared__ char sm[];
    const uint32_t sbase = smem_u32(sm);

    const int tid  = threadIdx.x;
    const int wid  = tid >> 5;
    const int lane = tid & 31;
    const int bn = blockIdx.x * BN;
    const int bm = blockIdx.y * BM;
    const bool useC2 = (g_anyC2 != 0);
    const int nK = useC2 ? 64 : 32;

    const int warp_m = wid & 3;      // 0..3 -> 32 rows each
    const int warp_n = wid >> 2;     // 0..3 -> 32 cols each

    float acc[2][4][4];
    #pragma unroll
    for (int mi = 0; mi < 2; mi++)
        #pragma unroll
        for (int ni = 0; ni < 4; ni++)
            #pragma unroll
            for (int q = 0; q < 4; q++) acc[mi][ni][q] = 0.0f;

    // A: 2048 16B-chunks/stage; B: 2048 -> 4 each per thread
    auto load_stage = [&](int ktL) {
        const int buf = ktL % NSTAGE;
        const int k0 = (ktL & 31) * BK;
        const __half *pA, *pB;
        if (ktL < 32) { pA = g_A1; pB = g_Wh; }
        else          { pA = g_A2; pB = g_Rh; }
        const uint32_t sA = sbase + buf * STAGE;
        const uint32_t sB = sA + A_BYTES;

        #pragma unroll
        for (int j = 0; j < 4; j++) {           // A: 128 rows x 16 chunks
            int id = tid + NTHR * j;
            int ar = id >> 4, ac = id & 15;
            size_t gA = (size_t)(bm + ar) * O_DIM + k0 + ac * 8;
            CP_ASYNC16(sA + ar * (LDA * 2) + ac * 16, pA + gA);
        }
        #pragma unroll
        for (int j = 0; j < 4; j++) {           // B: 128 rows x 16 chunks
            int id = tid + NTHR * j;
            int br = id >> 4, bc = id & 15;
            size_t gB = (size_t)(k0 + br) * I_DIM + bn + bc * 8;
            CP_ASYNC16(sB + br * (LDB * 2) + bc * 16, pB + gB);
        }
    };

    // prologue: 2 stages in flight
    load_stage(0); CP_COMMIT();
    load_stage(1); CP_COMMIT();

    const uint32_t aoff = (warp_m * 32 + (lane & 15)) * (LDA * 2) + (lane >> 4) * 16;
    // x4.trans: lanes 0-15 -> k-rows of n8 block p*2, lanes 16-31 -> block p*2+1
    const uint32_t boff = (lane & 15) * (LDB * 2) + warp_n * 64 + ((lane >> 4) << 4);

    for (int kt = 0; kt < nK; kt++) {
        // Outstanding groups (this thread): {kt, kt+1}.
        CP_WAIT1();             // my stage-kt copies retired
        __syncthreads();        // everyone's stage-kt data visible;
                                // all threads done with compute(kt-1)
        if (kt + 2 < nK) load_stage(kt + 2);   // overwrites buf (kt-1)%3: safe
        CP_COMMIT();

        const uint32_t sA = sbase + (kt % NSTAGE) * STAGE;
        const uint32_t sB = sA + A_BYTES;

        #pragma unroll
        for (int ks = 0; ks < 8; ks++) {
            uint32_t ah[2][4], bh[4][2];
            #pragma unroll
            for (int mi = 0; mi < 2; mi++) {
                uint32_t a = aoff + mi * 16 * (LDA * 2) + ks * 32;
                ldmx4(ah[mi], sA + a);
            }
            #pragma unroll
            for (int p = 0; p < 2; p++) {       // each x4t fills 2 ni fragments
                uint32_t r[4];
                uint32_t b = boff + ks * 16 * (LDB * 2) + p * 32;
                ldmx4t(r, sB + b);
                bh[p * 2 + 0][0] = r[0]; bh[p * 2 + 0][1] = r[1];
                bh[p * 2 + 1][0] = r[2]; bh[p * 2 + 1][1] = r[3];
            }
            #pragma unroll
            for (int mi = 0; mi < 2; mi++)
                #pragma unroll
                for (int ni = 0; ni < 4; ni++)
                    mma_f16(acc[mi][ni], ah[mi], bh[ni]);
        }
    }

    // ---- epilogue: add D[m], write float2 per fragment pair
    #pragma unroll
    for (int mi = 0; mi < 2; mi++) {
        const int r0 = bm + warp_m * 32 + mi * 16 + (lane >> 2);
        const int r1 = r0 + 8;
        const float d0 = g_D[r0];
        const float d1 = g_D[r1];
        #pragma unroll
        for (int ni = 0; ni < 4; ni++) {
            const int c = bn + warp_n * 32 + ni * 8 + (lane & 3) * 2;
            float2 v0 = {acc[mi][ni][0] + d0, acc[mi][ni][1] + d0};
            float2 v1 = {acc[mi][ni][2] + d1, acc[mi][ni][3] + d1};
            *(float2*)(out + (size_t)r0 * I_DIM + c) = v0;
            *(float2*)(out + (size_t)r1 * I_DIM + c) = v1;
        }
    }
}

// ===================== launch ==============================================
extern "C" void kernel_launch(void* const* d_in, const int* in_sizes, int n_in,
                              void* d_out, int out_size) {
    const float* last_uA = (const float*)d_in[0];  // [1, 512, 4096]
    const float* weight  = (const float*)d_in[1];  // [4096, 4096]
    const float* bias    = (const float*)d_in[2];  // [4096]
    const float* lbp     = (const float*)d_in[3];  // [1, 4096]
    const float* ubp     = (const float*)d_in[4];  // [1, 4096]
    const float* alpha   = (const float*)d_in[5];  // [1, 4096, 1]
    float* out = (float*)d_out;                    // uA then ubias

    cudaFuncSetAttribute(kern_gemm_mma,
                         cudaFuncAttributeMaxDynamicSharedMemorySize, SMEM_DYN);

    kern_prep_all<<<PREP_BLOCKS, 256>>>(weight, bias, lbp, ubp, alpha,
                                        last_uA, out + (size_t)S_DIM * I_DIM);
    kern_gemm_mma<<<dim3(I_DIM / BN, S_DIM / BM), NTHR, SMEM_DYN>>>(out);
}